// round 1
// baseline (speedup 1.0000x reference)
#include <cuda_runtime.h>
#include <cuda_bf16.h>

#define BB 32
#define TT 2000
#define HH 512
#define LL 256
#define H4 (HH/4)

// Scratch (device globals — no allocation allowed)
__device__ float g_w[BB*TT];     // per-frame weight toward its own token
__device__ int   g_fpos[BB*LL];  // frame index of k-th fire
__device__ float g_carry[BB*LL]; // carry weight into token k (remainds at fire k-1)
__device__ int   g_nf[BB];       // number of emitted tokens (<= L)

// ---------------- Phase 1: per-batch alpha scan ----------------
__global__ void __launch_bounds__(256) cif_scan_kernel(
    const float* __restrict__ alphas, const int* __restrict__ tlen)
{
    __shared__ float  sa[TT];
    __shared__ double ssum[8];
    __shared__ float  sscale;

    const int b = blockIdx.x;
    const float* arow = alphas + b * TT;

    // Cooperative load + f64 sum (closest to the "true" sum; reference uses an
    // unknown f32 tree order — f64 correctly-rounded-to-f32 is the best proxy).
    double acc = 0.0;
    for (int t = threadIdx.x; t < TT; t += blockDim.x) {
        float v = arow[t];
        sa[t] = v;
        acc += (double)v;
    }
    #pragma unroll
    for (int o = 16; o; o >>= 1) acc += __shfl_down_sync(0xFFFFFFFFu, acc, o);
    if ((threadIdx.x & 31) == 0) ssum[threadIdx.x >> 5] = acc;
    __syncthreads();
    if (threadIdx.x == 0) {
        double s = 0.0;
        #pragma unroll
        for (int i = 0; i < 8; i++) s += ssum[i];
        float sumf = (float)s;
        sscale = (float)tlen[b] / sumf;   // matches reference: num / sum (f32 div)
    }
    __syncthreads();
    const float scale = sscale;

    // Scale alphas in place (matches reference: alpha * scale, f32 mul)
    for (int t = threadIdx.x; t < TT; t += blockDim.x) sa[t] = sa[t] * scale;
    __syncthreads();

    // Sequential f32 scan, exact replay of the reference ordering.
    if (threadIdx.x == 0) {
        float I = 0.0f;
        int   k = 0;
        float* wrow = g_w + b * TT;
        g_carry[b * LL] = 0.0f;
        #pragma unroll 4
        for (int t = 0; t < TT; ++t) {
            float a    = sa[t];
            float dist = 1.0f - I;   // dist_completion BEFORE integrating
            I += a;
            bool fire = (I >= 0.95f);
            wrow[t] = fire ? dist : a;       // cur
            I -= fire ? 1.0f : 0.0f;         // exact subtract (Sterbenz range)
            if (fire) {
                if (k < LL)     g_fpos[b * LL + k]     = t;
                if (k + 1 < LL) g_carry[b * LL + k + 1] = a - dist;  // remainds
                k++;
            }
        }
        g_nf[b] = (k < LL) ? k : LL;
    }
}

// ---------------- Phase 2: weighted segmented reduction ----------------
// Block (k, b): out[b,k,:] = carry[k]*h[s] + sum_{t in (s, e]} w[t]*h[t]
__global__ void __launch_bounds__(128) cif_gather_kernel(
    const float* __restrict__ hidden, float* __restrict__ out)
{
    const int k  = blockIdx.x;
    const int b  = blockIdx.y;
    const int h4 = threadIdx.x;   // 0..127, 4 floats each -> H=512

    float4* o = (float4*)out + (size_t)(b * LL + k) * H4 + h4;

    const int nfb = g_nf[b];
    if (k >= nfb) {               // unemitted token -> zeros (out is poisoned)
        *o = make_float4(0.f, 0.f, 0.f, 0.f);
        return;
    }

    const float4* hid = (const float4*)hidden + (size_t)b * TT * H4 + h4;
    const float*  wrow = g_w + b * TT;

    const int e = g_fpos[b * LL + k];
    float4 acc = make_float4(0.f, 0.f, 0.f, 0.f);
    int t0;
    if (k == 0) {
        t0 = 0;
    } else {
        int   s  = g_fpos[b * LL + k - 1];
        float cw = g_carry[b * LL + k];
        float4 hv = hid[(size_t)s * H4];
        acc.x = cw * hv.x; acc.y = cw * hv.y;
        acc.z = cw * hv.z; acc.w = cw * hv.w;
        t0 = s + 1;
    }

    #pragma unroll 4
    for (int t = t0; t <= e; ++t) {
        float  w  = __ldg(wrow + t);
        float4 hv = hid[(size_t)t * H4];
        acc.x = fmaf(w, hv.x, acc.x);
        acc.y = fmaf(w, hv.y, acc.y);
        acc.z = fmaf(w, hv.z, acc.z);
        acc.w = fmaf(w, hv.w, acc.w);
    }
    *o = acc;
}

extern "C" void kernel_launch(void* const* d_in, const int* in_sizes, int n_in,
                              void* d_out, int out_size)
{
    const float* hidden = (const float*)d_in[0];   // [32,2000,512] f32
    const float* alphas = (const float*)d_in[1];   // [32,2000]     f32
    const int*   tlen   = (const int*)d_in[2];     // [32]          i32
    float*       out    = (float*)d_out;           // [32,256,512]  f32

    cif_scan_kernel<<<BB, 256>>>(alphas, tlen);
    dim3 grid(LL, BB);
    cif_gather_kernel<<<grid, 128>>>(hidden, out);
}

// round 2
// speedup vs baseline: 1.0899x; 1.0899x over previous
#include <cuda_runtime.h>
#include <cuda_bf16.h>

#define BB 32
#define TT 2000
#define HH 512
#define LL 256
#define LL1 (LL+1)          // +1 trash slot for branchless predicated stores
#define H4 (HH/4)
#define BPB 4               // batches per scan block (smem = TT*5*4 = 40KB)

// Scratch (device globals — no allocation allowed)
__device__ float g_wT[TT*BB];      // per-frame weight, TRANSPOSED [t*BB + b]
__device__ int   g_fpos[BB*LL1];   // frame index of k-th fire (row stride LL1)
__device__ float g_carry[BB*LL1];  // carry weight into token k
__device__ int   g_nf[BB];         // number of emitted tokens (<= LL)

// ---------------- Phase 1: SIMT serial alpha scans ----------------
// 8 blocks x 4 batches. Warps 0-3 stage+sum their batch; lanes 0-3 of warp 0
// then run 4 fully branchless serial f32 chains (exact reference replay).
__global__ void __launch_bounds__(128) cif_scan_kernel(
    const float* __restrict__ alphas, const int* __restrict__ tlen)
{
    __shared__ float sa[TT*5];     // transposed, pad-5: sa[t*5 + bb]
    __shared__ float sscale[BPB];

    const int b0  = blockIdx.x * BPB;
    const int wid = threadIdx.x >> 5;
    const int lid = threadIdx.x & 31;

    // Stage + f64 sum: warp w handles batch b0+w (coalesced read, padded STS)
    if (wid < BPB) {
        const float* arow = alphas + (b0 + wid) * TT;
        double acc = 0.0;
        for (int t = lid; t < TT; t += 32) {
            float v = arow[t];
            sa[t*5 + wid] = v;
            acc += (double)v;
        }
        #pragma unroll
        for (int o = 16; o; o >>= 1) acc += __shfl_down_sync(0xFFFFFFFFu, acc, o);
        if (lid == 0)
            sscale[wid] = (float)tlen[b0 + wid] / (float)acc;  // f32 div as ref
    }
    __syncthreads();

    // Branchless serial scan: lanes 0..3, each its own batch.
    if (threadIdx.x < BPB) {
        const int   bb    = threadIdx.x;
        const int   b     = b0 + bb;
        const float scale = sscale[bb];
        float* wT    = g_wT;
        int*   fpos  = g_fpos  + b * LL1;
        float* carry = g_carry + b * LL1;

        float I = 0.0f;
        int   k = 0;
        #pragma unroll 4
        for (int t = 0; t < TT; ++t) {
            float a    = sa[t*5 + bb] * scale;   // off-chain FMUL
            float I1   = I + a;                  // chain FADD
            bool  fire = (I1 >= 0.95f);          // FSETP (parallel w/ I1m1)
            float I1m1 = I1 - 1.0f;              // off-chain FADD
            float w    = fire ? (1.0f - I) : a;  // FSEL (dist computed off-chain)
            I          = fire ? I1m1 : I1;       // FSEL pred-as-data -> 12cyc chain

            wT[t*BB + b] = w;                    // coalesced-ish STG, off-chain

            // Branchless bookkeeping: store to trash slot LL when not firing.
            int ik  = k < LL  ? k   : LL;        // clamp (k==LL hits trash too)
            int ic  = k+1 < LL ? k+1 : LL;
            fpos [fire ? ik : LL] = t;
            carry[fire ? ic : LL] = a - w;       // remainds = alpha - cur
            k += (int)fire;
        }
        g_nf[b] = (k < LL) ? k : LL;
    }
}

// ---------------- Phase 2: weighted segmented reduction ----------------
// Block (k, b): out[b,k,:] = carry[k]*h[s] + sum_{t in (s, e]} w[t]*h[t]
__global__ void __launch_bounds__(128) cif_gather_kernel(
    const float* __restrict__ hidden, float* __restrict__ out)
{
    const int k  = blockIdx.x;
    const int b  = blockIdx.y;
    const int h4 = threadIdx.x;   // 0..127, one float4 each -> H=512

    float4* o = (float4*)out + (size_t)(b * LL + k) * H4 + h4;

    const int nfb = g_nf[b];
    if (k >= nfb) {               // unemitted token -> zeros (out is poisoned)
        *o = make_float4(0.f, 0.f, 0.f, 0.f);
        return;
    }

    const float4* hid = (const float4*)hidden + (size_t)b * TT * H4 + h4;

    const int e = g_fpos[b * LL1 + k];
    float4 acc = make_float4(0.f, 0.f, 0.f, 0.f);
    int t0;
    if (k == 0) {
        t0 = 0;
    } else {
        int   s  = g_fpos[b * LL1 + k - 1];
        float cw = g_carry[b * LL1 + k];
        float4 hv = hid[(size_t)s * H4];
        acc.x = cw * hv.x; acc.y = cw * hv.y;
        acc.z = cw * hv.z; acc.w = cw * hv.w;
        t0 = s + 1;
    }

    #pragma unroll 8
    for (int t = t0; t <= e; ++t) {
        float  w  = __ldg(&g_wT[t*BB + b]);
        float4 hv = hid[(size_t)t * H4];
        acc.x = fmaf(w, hv.x, acc.x);
        acc.y = fmaf(w, hv.y, acc.y);
        acc.z = fmaf(w, hv.z, acc.z);
        acc.w = fmaf(w, hv.w, acc.w);
    }
    *o = acc;
}

extern "C" void kernel_launch(void* const* d_in, const int* in_sizes, int n_in,
                              void* d_out, int out_size)
{
    const float* hidden = (const float*)d_in[0];   // [32,2000,512] f32
    const float* alphas = (const float*)d_in[1];   // [32,2000]     f32
    const int*   tlen   = (const int*)d_in[2];     // [32]          i32
    float*       out    = (float*)d_out;           // [32,256,512]  f32

    cif_scan_kernel<<<BB/BPB, 128>>>(alphas, tlen);
    dim3 grid(LL, BB);
    cif_gather_kernel<<<grid, 128>>>(hidden, out);
}